// round 4
// baseline (speedup 1.0000x reference)
#include <cuda_runtime.h>

#define HWD   224
#define NPIX  (HWD*HWD)        // 50176
#define BB    2
#define C1    64
#define EE    768
#define MM    196
#define KK    (BB*MM)          // 392
#define PADW  228
#define BNEPS 1e-5f

// ---- static device scratch (no allocation allowed) ----
__device__ float g_xpad[BB*PADW*PADW*C1];     // conv1 output, padded NHWC (26.6MB)
__device__ float g_feats[77070336];           // conv2 output NHWC [B][HW][E] (308MB)
__device__ float g_w2t[9*C1*EE];              // conv2 weights [t][cin][cout], BN-folded
__device__ float g_fconst[EE];                // folded conv2 bias+BN shift
__device__ int   g_cnt[KK];
__device__ float g_sim[KK];
__device__ float g_wk[KK];
__device__ int   g_off[KK+1];
__device__ int   g_cur[KK];
__device__ int   g_plist[BB*NPIX];
__device__ float g_concat[KK*2*EE];           // [K][mean(768) | max(768)]

// ------------------------------------------------------------------
__global__ void k_zero() {
    float4* p = (float4*)g_xpad;
    const int n4 = (BB*PADW*PADW*C1)/4;
    for (int i = blockIdx.x*blockDim.x + threadIdx.x; i < n4; i += gridDim.x*blockDim.x)
        p[i] = make_float4(0.f,0.f,0.f,0.f);
    // FIX: KK=392 > blockDim; must grid-stride so ALL counters reset every replay
    if (blockIdx.x == 0) {
        for (int i = threadIdx.x; i < KK; i += blockDim.x) {
            g_cnt[i] = 0; g_sim[i] = 0.f; g_cur[i] = 0;
        }
    }
}

// ------------------------------------------------------------------
__global__ void k_prep_fconst(const float* cb, const float* bg, const float* bb_,
                              const float* bm, const float* bv) {
    int c = threadIdx.x;
    if (c < EE) {
        float inv = bg[c] * rsqrtf(bv[c] + BNEPS);
        g_fconst[c] = cb[c]*inv + bb_[c] - bm[c]*inv;
    }
}

// transpose conv2_w [cout][cin][3][3] -> [t][cin][cout], scaled by BN inv
__global__ void k_prep_w2t(const float* w, const float* bg, const float* bv) {
    int i = blockIdx.x*blockDim.x + threadIdx.x;
    const int n = 9*C1*EE;
    if (i < n) {
        int cout = i % EE;
        int r    = i / EE;       // t*64 + cin
        int cin  = r % C1;
        int t    = r / C1;
        float inv = __ldg(&bg[cout]) * rsqrtf(__ldg(&bv[cout]) + BNEPS);
        g_w2t[i] = __ldg(&w[cout*(C1*9) + cin*9 + t]) * inv;
    }
}

// ------------------------------------------------------------------
// conv1 3->64, 3x3 pad1 + BN + ReLU, write into padded NHWC buffer
__global__ void k_conv1(const float* img, const float* w, const float* bias,
                        const float* bg, const float* bb_, const float* bm, const float* bv) {
    int gid = blockIdx.x*blockDim.x + threadIdx.x;   // B*NPIX*8 threads
    int cg  = gid & 7;
    int pix = gid >> 3;
    if (pix >= BB*NPIX) return;
    int b = pix / NPIX, p = pix % NPIX;
    int y = p / HWD, x = p % HWD;

    float in[27];
    #pragma unroll
    for (int ci = 0; ci < 3; ci++)
        #pragma unroll
        for (int ky = 0; ky < 3; ky++)
            #pragma unroll
            for (int kx = 0; kx < 3; kx++) {
                int yy = y + ky - 1, xx = x + kx - 1;
                float v = 0.f;
                if (yy >= 0 && yy < HWD && xx >= 0 && xx < HWD)
                    v = __ldg(&img[((b*3 + ci)*HWD + yy)*HWD + xx]);
                in[ci*9 + ky*3 + kx] = v;
            }
    int c0 = cg*8;
    float o[8];
    #pragma unroll
    for (int j = 0; j < 8; j++) {
        int c = c0 + j;
        float acc = 0.f;
        #pragma unroll
        for (int q = 0; q < 27; q++) acc += in[q] * __ldg(&w[c*27 + q]);
        float inv = __ldg(&bg[c]) * rsqrtf(__ldg(&bv[c]) + BNEPS);
        float v = (acc + __ldg(&bias[c]))*inv + __ldg(&bb_[c]) - __ldg(&bm[c])*inv;
        o[j] = fmaxf(v, 0.f);
    }
    float* dst = &g_xpad[(((size_t)b*PADW + y + 2)*PADW + x + 2)*C1 + c0];
    ((float4*)dst)[0] = make_float4(o[0],o[1],o[2],o[3]);
    ((float4*)dst)[1] = make_float4(o[4],o[5],o[6],o[7]);
}

// ------------------------------------------------------------------
// gray -> edge conv -> gradient/similarity; per-block smem histogram of
// counts & similarity sums; also write gradient_map and segments outputs.
__global__ void k_edge(const float* img, const int* seg, const float* ew,
                       float* out, int goff, int soff) {
    __shared__ int   scnt[MM];
    __shared__ float ssim[MM];
    int tid = threadIdx.x;
    if (tid < MM) { scnt[tid] = 0; ssim[tid] = 0.f; }
    __syncthreads();

    int gid = blockIdx.x*256 + tid;       // block stays within one batch
    int b = gid / NPIX, p = gid % NPIX;
    int y = p / HWD, x = p % HWD;

    float e0 = 0.f, e1 = 0.f;
    #pragma unroll
    for (int ky = 0; ky < 3; ky++)
        #pragma unroll
        for (int kx = 0; kx < 3; kx++) {
            int yy = y + ky - 1, xx = x + kx - 1;
            float gr = 0.f;
            if (yy >= 0 && yy < HWD && xx >= 0 && xx < HWD) {
                int base = (b*3*HWD + yy)*HWD + xx;
                gr = (__ldg(&img[base]) + __ldg(&img[base + NPIX]) + __ldg(&img[base + 2*NPIX])) * (1.f/3.f);
            }
            e0 += gr * __ldg(&ew[ky*3 + kx]);
            e1 += gr * __ldg(&ew[9 + ky*3 + kx]);
        }
    float grad = sqrtf(e0*e0 + e1*e1 + 1e-8f);
    float sim  = fminf(fmaxf(1.f - grad, 0.f), 1.f);
    int s = seg[gid];
    if (goff >= 0) out[goff + gid] = grad;
    if (soff >= 0) out[soff + gid] = (float)s;
    atomicAdd(&scnt[s], 1);
    atomicAdd(&ssim[s], sim);
    __syncthreads();
    if (tid < MM) {
        if (scnt[tid]) atomicAdd(&g_cnt[b*MM + tid], scnt[tid]);
        if (ssim[tid] != 0.f) atomicAdd(&g_sim[b*MM + tid], ssim[tid]);
    }
}

// ------------------------------------------------------------------
__global__ void k_scan() {
    __shared__ int s[512];
    int tid = threadIdx.x;
    int v = (tid < KK) ? g_cnt[tid] : 0;
    s[tid] = v;
    __syncthreads();
    for (int d = 1; d < 512; d <<= 1) {
        int t = (tid >= d) ? s[tid - d] : 0;
        __syncthreads();
        s[tid] += t;
        __syncthreads();
    }
    if (tid < KK) {
        g_off[tid] = s[tid] - v;
        g_wk[tid]  = g_sim[tid] / fmaxf((float)v, 1.f);
    }
    if (tid == 0) g_off[KK] = s[511];
}

__global__ void k_scatter(const int* seg) {
    int gid = blockIdx.x*256 + threadIdx.x;
    int b = gid / NPIX, p = gid % NPIX;
    int k = b*MM + seg[gid];
    int pos = atomicAdd(&g_cur[k], 1);
    g_plist[g_off[k] + pos] = p;
}

// ------------------------------------------------------------------
// conv2: 64->768, 3x3 dilation 2, BN+ReLU folded. Tile 16x16 pix x 32 couts.
#define TS_IN  (400*68)      // 20x20 pixels, stride 68 floats
#define TS_W   (9*64*32)
__global__ void __launch_bounds__(256, 1) k_conv2() {
    extern __shared__ float sm[];
    float* in_s = sm;
    float* w_s  = sm + TS_IN;

    int b   = blockIdx.z;
    int ty  = blockIdx.x / 14, tx = blockIdx.x % 14;
    int c0  = blockIdx.y * 32;
    int tid = threadIdx.x;

    // load input tile (20x20x64) from padded buffer; pixel stride 68 floats (17 f4)
    {
        const float4* src4 = (const float4*)g_xpad;
        float4* in4 = (float4*)in_s;
        #pragma unroll
        for (int u = tid; u < 400*16; u += 256) {
            int pix = u >> 4, c4 = u & 15;
            int iy = pix / 20, ix = pix % 20;
            int ry = ty*16 + iy, rx = tx*16 + ix;
            in4[pix*17 + c4] = src4[(((size_t)b*PADW + ry)*PADW + rx)*16 + c4];
        }
    }
    // load weights: w_s[t][cin][co32]
    {
        const float4* w4 = (const float4*)g_w2t;
        float4* ws4 = (float4*)w_s;
        #pragma unroll
        for (int e4 = tid; e4 < TS_W/4; e4 += 256) {
            int co4 = e4 & 7, r = e4 >> 3;          // r = t*64+cin
            ws4[e4] = w4[r*(EE/4) + (c0 >> 2) + co4];
        }
    }
    __syncthreads();

    int cg = tid & 3;
    int pg = tid >> 2;          // 0..63 -> pixel (oy, ox); 4 pixels strided by 4 rows
    int oy = pg >> 4, ox = pg & 15;

    float acc[4][8];
    #pragma unroll
    for (int i = 0; i < 4; i++)
        #pragma unroll
        for (int j = 0; j < 8; j++) acc[i][j] = 0.f;

    const float4* in4 = (const float4*)in_s;

    #pragma unroll 1
    for (int t = 0; t < 9; t++) {
        int ky = t / 3, kx = t - ky*3;
        const float4* wrow = (const float4*)(w_s + t*2048);
        int ib0 = ((oy + 2*ky)*20 + ox + 2*kx)*17;
        #pragma unroll
        for (int c4 = 0; c4 < 16; c4++) {
            float4 xv0 = in4[ib0 + c4];
            float4 xv1 = in4[ib0 + 1360 + c4];
            float4 xv2 = in4[ib0 + 2720 + c4];
            float4 xv3 = in4[ib0 + 4080 + c4];
            const float* xp0 = (const float*)&xv0;
            const float* xp1 = (const float*)&xv1;
            const float* xp2 = (const float*)&xv2;
            const float* xp3 = (const float*)&xv3;
            #pragma unroll
            for (int cc = 0; cc < 4; cc++) {
                float4 wlo = wrow[(c4*4 + cc)*8 + cg*2];
                float4 whi = wrow[(c4*4 + cc)*8 + cg*2 + 1];
                float a0 = xp0[cc], a1 = xp1[cc], a2 = xp2[cc], a3 = xp3[cc];
                acc[0][0] += a0*wlo.x; acc[0][1] += a0*wlo.y; acc[0][2] += a0*wlo.z; acc[0][3] += a0*wlo.w;
                acc[0][4] += a0*whi.x; acc[0][5] += a0*whi.y; acc[0][6] += a0*whi.z; acc[0][7] += a0*whi.w;
                acc[1][0] += a1*wlo.x; acc[1][1] += a1*wlo.y; acc[1][2] += a1*wlo.z; acc[1][3] += a1*wlo.w;
                acc[1][4] += a1*whi.x; acc[1][5] += a1*whi.y; acc[1][6] += a1*whi.z; acc[1][7] += a1*whi.w;
                acc[2][0] += a2*wlo.x; acc[2][1] += a2*wlo.y; acc[2][2] += a2*wlo.z; acc[2][3] += a2*wlo.w;
                acc[2][4] += a2*whi.x; acc[2][5] += a2*whi.y; acc[2][6] += a2*whi.z; acc[2][7] += a2*whi.w;
                acc[3][0] += a3*wlo.x; acc[3][1] += a3*wlo.y; acc[3][2] += a3*wlo.z; acc[3][3] += a3*wlo.w;
                acc[3][4] += a3*whi.x; acc[3][5] += a3*whi.y; acc[3][6] += a3*whi.z; acc[3][7] += a3*whi.w;
            }
        }
    }

    // epilogue: + folded bias, ReLU, store NHWC feats
    #pragma unroll
    for (int i = 0; i < 4; i++) {
        int y = ty*16 + oy + 4*i;
        int x = tx*16 + ox;
        size_t base = ((size_t)b*NPIX + (size_t)y*HWD + x)*EE + c0 + cg*8;
        float o[8];
        #pragma unroll
        for (int j = 0; j < 8; j++)
            o[j] = fmaxf(acc[i][j] + g_fconst[c0 + cg*8 + j], 0.f);
        ((float4*)&g_feats[base])[0] = make_float4(o[0],o[1],o[2],o[3]);
        ((float4*)&g_feats[base])[1] = make_float4(o[4],o[5],o[6],o[7]);
    }
}

// ------------------------------------------------------------------
// per-(b,seg) mean/max pooling over pixel list; each thread owns 3 channels
__global__ void k_pool() {
    __shared__ int sp[256];
    int k = blockIdx.x;
    int b = k / MM;
    int tid = threadIdx.x;
    int cnt = g_cnt[k];
    int off = g_off[k];
    const float* fb = g_feats + (size_t)b*NPIX*EE;

    float s0=0.f, s1=0.f, s2=0.f, m0=0.f, m1=0.f, m2=0.f;
    for (int base = 0; base < cnt; base += 256) {
        int nchunk = min(256, cnt - base);
        __syncthreads();
        if (tid < nchunk) sp[tid] = g_plist[off + base + tid];
        __syncthreads();
        int i = 0;
        for (; i + 1 < nchunk; i += 2) {
            const float* f0 = fb + (size_t)sp[i]*EE + tid;
            const float* f1 = fb + (size_t)sp[i+1]*EE + tid;
            float a0 = f0[0], b0 = f0[256], c0v = f0[512];
            float a1 = f1[0], b1 = f1[256], c1v = f1[512];
            s0 += a0 + a1; s1 += b0 + b1; s2 += c0v + c1v;
            m0 = fmaxf(m0, fmaxf(a0, a1));
            m1 = fmaxf(m1, fmaxf(b0, b1));
            m2 = fmaxf(m2, fmaxf(c0v, c1v));
        }
        if (i < nchunk) {
            const float* f0 = fb + (size_t)sp[i]*EE + tid;
            float a0 = f0[0], b0 = f0[256], c0v = f0[512];
            s0 += a0; s1 += b0; s2 += c0v;
            m0 = fmaxf(m0, a0); m1 = fmaxf(m1, b0); m2 = fmaxf(m2, c0v);
        }
    }
    float n = fmaxf((float)cnt, 1.f);
    float* dst = g_concat + (size_t)k*1536;
    dst[tid]        = s0/n;  dst[256 + tid]  = s1/n;  dst[512 + tid]  = s2/n;
    dst[768 + tid]  = m0;    dst[1024 + tid] = m1;    dst[1280 + tid] = m2;
}

// ------------------------------------------------------------------
// fused = concat @ fusion_w^T + b, *W_k, + positional embedding
__global__ void k_fuse(const float* fw, const float* fbias, const float* pw,
                       const float* pb, const float* cent, float* out) {
    __shared__ float As[16][68];
    __shared__ float Bs[16][68];
    int tid = threadIdx.x;
    int d0 = blockIdx.x * 64;
    int r0 = blockIdx.y * 64;
    int tx = tid % 16, ty2 = tid / 16;

    float acc[4][4];
    #pragma unroll
    for (int i = 0; i < 4; i++)
        #pragma unroll
        for (int j = 0; j < 4; j++) acc[i][j] = 0.f;

    for (int kk = 0; kk < 2*EE; kk += 16) {
        {
            int ar = tid >> 2, ac4 = tid & 3;
            int r = r0 + ar;
            float4 v = make_float4(0.f,0.f,0.f,0.f);
            if (r < KK)
                v = ((const float4*)(g_concat + (size_t)r*1536 + kk))[ac4];
            As[ac4*4+0][ar] = v.x; As[ac4*4+1][ar] = v.y;
            As[ac4*4+2][ar] = v.z; As[ac4*4+3][ar] = v.w;
        }
        {
            int dd = tid >> 2, cc4 = tid & 3;
            float4 v = ((const float4*)(fw + (size_t)(d0 + dd)*1536 + kk))[cc4];
            Bs[cc4*4+0][dd] = v.x; Bs[cc4*4+1][dd] = v.y;
            Bs[cc4*4+2][dd] = v.z; Bs[cc4*4+3][dd] = v.w;
        }
        __syncthreads();
        #pragma unroll
        for (int q = 0; q < 16; q++) {
            float4 a = *(const float4*)&As[q][ty2*4];
            float4 bv = *(const float4*)&Bs[q][tx*4];
            const float* ap = (const float*)&a;
            const float* bp = (const float*)&bv;
            #pragma unroll
            for (int i = 0; i < 4; i++)
                #pragma unroll
                for (int j = 0; j < 4; j++)
                    acc[i][j] += ap[i] * bp[j];
        }
        __syncthreads();
    }

    #pragma unroll
    for (int i = 0; i < 4; i++) {
        int r = r0 + ty2*4 + i;
        if (r >= KK) continue;
        float wk = g_wk[r];
        float cx = __ldg(&cent[r*2 + 0]) * (1.f/224.f);
        float cy = __ldg(&cent[r*2 + 1]) * (1.f/224.f);
        #pragma unroll
        for (int j = 0; j < 4; j++) {
            int d = d0 + tx*4 + j;
            float v = (acc[i][j] + __ldg(&fbias[d])) * wk;
            v += cx*__ldg(&pw[d*2 + 0]) + cy*__ldg(&pw[d*2 + 1]) + __ldg(&pb[d]);
            out[(size_t)r*EE + d] = v;
        }
    }
}

// ------------------------------------------------------------------
extern "C" void kernel_launch(void* const* d_in, const int* in_sizes, int n_in,
                              void* d_out, int out_size) {
    const float* img   = (const float*)d_in[0];
    const int*   seg   = (const int*)d_in[1];
    const float* cent  = (const float*)d_in[2];
    const float* c1w   = (const float*)d_in[3];
    const float* c1b   = (const float*)d_in[4];
    const float* bn1g  = (const float*)d_in[5];
    const float* bn1b  = (const float*)d_in[6];
    const float* bn1m  = (const float*)d_in[7];
    const float* bn1v  = (const float*)d_in[8];
    const float* c2w   = (const float*)d_in[9];
    const float* c2b   = (const float*)d_in[10];
    const float* bn2g  = (const float*)d_in[11];
    const float* bn2b  = (const float*)d_in[12];
    const float* bn2m  = (const float*)d_in[13];
    const float* bn2v  = (const float*)d_in[14];
    const float* edgew = (const float*)d_in[15];
    const float* posw  = (const float*)d_in[16];
    const float* posb  = (const float*)d_in[17];
    const float* fusw  = (const float*)d_in[18];
    const float* fusb  = (const float*)d_in[19];
    float* out = (float*)d_out;
    (void)n_in; (void)in_sizes;

    const int FINAL_N = BB*MM*EE;          // 301056
    int goff = (out_size >= FINAL_N + BB*NPIX)   ? FINAL_N : -1;
    int soff = (out_size >= FINAL_N + 2*BB*NPIX) ? FINAL_N + BB*NPIX : -1;

    const int smem2 = (TS_IN + TS_W) * (int)sizeof(float);   // 182528
    cudaFuncSetAttribute(k_conv2, cudaFuncAttributeMaxDynamicSharedMemorySize, smem2);

    k_zero<<<1024, 256>>>();
    k_prep_fconst<<<1, EE>>>(c2b, bn2g, bn2b, bn2m, bn2v);
    k_prep_w2t<<<(9*C1*EE + 255)/256, 256>>>(c2w, bn2g, bn2v);
    k_conv1<<<(BB*NPIX*8)/256, 256>>>(img, c1w, c1b, bn1g, bn1b, bn1m, bn1v);
    k_edge<<<BB*NPIX/256, 256>>>(img, seg, edgew, out, goff, soff);
    k_scan<<<1, 512>>>();
    k_scatter<<<BB*NPIX/256, 256>>>(seg);
    k_conv2<<<dim3(196, 24, BB), 256, smem2>>>();
    k_pool<<<KK, 256>>>();
    k_fuse<<<dim3(EE/64, (KK + 63)/64), 256>>>(fusw, fusb, posw, posb, cent, out);
}

// round 5
// speedup vs baseline: 1.0690x; 1.0690x over previous
#include <cuda_runtime.h>

#define HWD   224
#define NPIX  (HWD*HWD)        // 50176
#define BB    2
#define C1    64
#define EE    768
#define MM    196
#define KK    (BB*MM)          // 392
#define PADW  228
#define BNEPS 1e-5f

// ---- static device scratch (no allocation allowed) ----
__device__ float g_xpad[BB*PADW*PADW*C1];     // conv1 output, padded NHWC (26.6MB)
__device__ float g_feats[77070336];           // conv2 output NHWC [B][HW][E] (308MB)
__device__ float g_w2t[9*C1*EE];              // conv2 weights [t][cin][cout], BN-folded
__device__ float g_fconst[EE];                // folded conv2 bias+BN shift
__device__ int   g_cnt[KK];
__device__ float g_sim[KK];
__device__ float g_wk[KK];
__device__ int   g_off[KK+1];
__device__ int   g_cur[KK];
__device__ int   g_plist[BB*NPIX];
__device__ float g_concat[KK*2*EE];           // [K][mean(768) | max(768)]

// packed fp32x2 helpers (sm_100+; ptxas never auto-fuses these)
#define FMA_F32X2(acc, a, b) \
    asm("fma.rn.f32x2 %0, %1, %2, %0;" : "+l"(acc) : "l"(a), "l"(b))
#define PACK_AA(out, a) \
    asm("mov.b64 %0, {%1, %1};" : "=l"(out) : "f"(a))
#define UNPACK2(lo, hi, in) \
    asm("mov.b64 {%0, %1}, %2;" : "=f"(lo), "=f"(hi) : "l"(in))

// ------------------------------------------------------------------
__global__ void k_zero() {
    float4* p = (float4*)g_xpad;
    const int n4 = (BB*PADW*PADW*C1)/4;
    for (int i = blockIdx.x*blockDim.x + threadIdx.x; i < n4; i += gridDim.x*blockDim.x)
        p[i] = make_float4(0.f,0.f,0.f,0.f);
    if (blockIdx.x == 0) {
        for (int i = threadIdx.x; i < KK; i += blockDim.x) {
            g_cnt[i] = 0; g_sim[i] = 0.f; g_cur[i] = 0;
        }
    }
}

// ------------------------------------------------------------------
__global__ void k_prep_fconst(const float* cb, const float* bg, const float* bb_,
                              const float* bm, const float* bv) {
    int c = threadIdx.x;
    if (c < EE) {
        float inv = bg[c] * rsqrtf(bv[c] + BNEPS);
        g_fconst[c] = cb[c]*inv + bb_[c] - bm[c]*inv;
    }
}

// transpose conv2_w [cout][cin][3][3] -> [t][cin][cout], scaled by BN inv
__global__ void k_prep_w2t(const float* w, const float* bg, const float* bv) {
    int i = blockIdx.x*blockDim.x + threadIdx.x;
    const int n = 9*C1*EE;
    if (i < n) {
        int cout = i % EE;
        int r    = i / EE;       // t*64 + cin
        int cin  = r % C1;
        int t    = r / C1;
        float inv = __ldg(&bg[cout]) * rsqrtf(__ldg(&bv[cout]) + BNEPS);
        g_w2t[i] = __ldg(&w[cout*(C1*9) + cin*9 + t]) * inv;
    }
}

// ------------------------------------------------------------------
// conv1 3->64, 3x3 pad1 + BN + ReLU, write into padded NHWC buffer
__global__ void k_conv1(const float* img, const float* w, const float* bias,
                        const float* bg, const float* bb_, const float* bm, const float* bv) {
    int gid = blockIdx.x*blockDim.x + threadIdx.x;   // B*NPIX*8 threads
    int cg  = gid & 7;
    int pix = gid >> 3;
    if (pix >= BB*NPIX) return;
    int b = pix / NPIX, p = pix % NPIX;
    int y = p / HWD, x = p % HWD;

    float in[27];
    #pragma unroll
    for (int ci = 0; ci < 3; ci++)
        #pragma unroll
        for (int ky = 0; ky < 3; ky++)
            #pragma unroll
            for (int kx = 0; kx < 3; kx++) {
                int yy = y + ky - 1, xx = x + kx - 1;
                float v = 0.f;
                if (yy >= 0 && yy < HWD && xx >= 0 && xx < HWD)
                    v = __ldg(&img[((b*3 + ci)*HWD + yy)*HWD + xx]);
                in[ci*9 + ky*3 + kx] = v;
            }
    int c0 = cg*8;
    float o[8];
    #pragma unroll
    for (int j = 0; j < 8; j++) {
        int c = c0 + j;
        float acc = 0.f;
        #pragma unroll
        for (int q = 0; q < 27; q++) acc += in[q] * __ldg(&w[c*27 + q]);
        float inv = __ldg(&bg[c]) * rsqrtf(__ldg(&bv[c]) + BNEPS);
        float v = (acc + __ldg(&bias[c]))*inv + __ldg(&bb_[c]) - __ldg(&bm[c])*inv;
        o[j] = fmaxf(v, 0.f);
    }
    float* dst = &g_xpad[(((size_t)b*PADW + y + 2)*PADW + x + 2)*C1 + c0];
    ((float4*)dst)[0] = make_float4(o[0],o[1],o[2],o[3]);
    ((float4*)dst)[1] = make_float4(o[4],o[5],o[6],o[7]);
}

// ------------------------------------------------------------------
__global__ void k_edge(const float* img, const int* seg, const float* ew,
                       float* out, int goff, int soff) {
    __shared__ int   scnt[MM];
    __shared__ float ssim[MM];
    int tid = threadIdx.x;
    if (tid < MM) { scnt[tid] = 0; ssim[tid] = 0.f; }
    __syncthreads();

    int gid = blockIdx.x*256 + tid;       // block stays within one batch
    int b = gid / NPIX, p = gid % NPIX;
    int y = p / HWD, x = p % HWD;

    float e0 = 0.f, e1 = 0.f;
    #pragma unroll
    for (int ky = 0; ky < 3; ky++)
        #pragma unroll
        for (int kx = 0; kx < 3; kx++) {
            int yy = y + ky - 1, xx = x + kx - 1;
            float gr = 0.f;
            if (yy >= 0 && yy < HWD && xx >= 0 && xx < HWD) {
                int base = (b*3*HWD + yy)*HWD + xx;
                gr = (__ldg(&img[base]) + __ldg(&img[base + NPIX]) + __ldg(&img[base + 2*NPIX])) * (1.f/3.f);
            }
            e0 += gr * __ldg(&ew[ky*3 + kx]);
            e1 += gr * __ldg(&ew[9 + ky*3 + kx]);
        }
    float grad = sqrtf(e0*e0 + e1*e1 + 1e-8f);
    float sim  = fminf(fmaxf(1.f - grad, 0.f), 1.f);
    int s = seg[gid];
    if (goff >= 0) out[goff + gid] = grad;
    if (soff >= 0) out[soff + gid] = (float)s;
    atomicAdd(&scnt[s], 1);
    atomicAdd(&ssim[s], sim);
    __syncthreads();
    if (tid < MM) {
        if (scnt[tid]) atomicAdd(&g_cnt[b*MM + tid], scnt[tid]);
        if (ssim[tid] != 0.f) atomicAdd(&g_sim[b*MM + tid], ssim[tid]);
    }
}

// ------------------------------------------------------------------
__global__ void k_scan() {
    __shared__ int s[512];
    int tid = threadIdx.x;
    int v = (tid < KK) ? g_cnt[tid] : 0;
    s[tid] = v;
    __syncthreads();
    for (int d = 1; d < 512; d <<= 1) {
        int t = (tid >= d) ? s[tid - d] : 0;
        __syncthreads();
        s[tid] += t;
        __syncthreads();
    }
    if (tid < KK) {
        g_off[tid] = s[tid] - v;
        g_wk[tid]  = g_sim[tid] / fmaxf((float)v, 1.f);
    }
    if (tid == 0) g_off[KK] = s[511];
}

__global__ void k_scatter(const int* seg) {
    int gid = blockIdx.x*256 + threadIdx.x;
    int b = gid / NPIX, p = gid % NPIX;
    int k = b*MM + seg[gid];
    int pos = atomicAdd(&g_cur[k], 1);
    g_plist[g_off[k] + pos] = p;
}

// ------------------------------------------------------------------
// conv2: 64->768, 3x3 dil=2, BN+ReLU folded. FFMA2 (fp32x2) version.
// Tile: 16x16 pixels x 64 couts. Thread: 8 pixels x 8 couts (32 packed accs).
// Weights double-buffered per tap (16KB each); input tile 20x20x64 resident.
#define TS_IN   (400*68)          // floats; 27200 f4
#define WTAP_F4 1024              // 64 cin x 64 cout = 4096 floats = 1024 f4
#define SMEM2_B ((TS_IN + 2*4096)*4)   // 141568 bytes

__global__ void __launch_bounds__(256, 1) k_conv2() {
    extern __shared__ float sm[];
    float4* in4 = (float4*)sm;                        // input tile
    float4* wb0 = (float4*)(sm + TS_IN);              // tap buffer 0
    float4* wb1 = (float4*)(sm + TS_IN + 4096);       // tap buffer 1

    int b   = blockIdx.z;
    int ty  = blockIdx.x / 14, tx = blockIdx.x % 14;
    int c0  = blockIdx.y * 64;
    int tid = threadIdx.x;

    // ---- load input tile (20x20x64), pixel stride 17 f4 ----
    {
        const float4* src4 = (const float4*)g_xpad;
        #pragma unroll
        for (int u = tid; u < 400*16; u += 256) {
            int pix = u >> 4, c4 = u & 15;
            int iy = pix / 20, ix = pix % 20;
            in4[pix*17 + c4] = src4[(((size_t)b*PADW + ty*16 + iy)*PADW + tx*16 + ix)*16 + c4];
        }
    }
    // ---- prologue: tap 0 weights -> wb0 ----
    const float4* w4 = (const float4*)g_w2t;
    {
        #pragma unroll
        for (int q = 0; q < 4; q++) {
            int u = q*256 + tid;              // 0..1023
            int cin = u >> 4, co4 = u & 15;
            wb0[u] = w4[(size_t)cin*192 + (c0 >> 2) + co4];
        }
    }
    __syncthreads();

    int cg = tid & 7;            // cout group (8 couts)
    int pg = tid >> 3;           // 0..31
    int oy = pg >> 4, ox = pg & 15;   // pixel rows oy+2*i, i=0..7

    unsigned long long acc[8][4];
    #pragma unroll
    for (int i = 0; i < 8; i++)
        #pragma unroll
        for (int j = 0; j < 4; j++) acc[i][j] = 0ull;

    union F4U2 { float4 f; unsigned long long u[2]; };

    #pragma unroll 1
    for (int t = 0; t < 9; t++) {
        // prefetch next tap into registers (latency hidden by compute below)
        float4 pf[4];
        if (t < 8) {
            #pragma unroll
            for (int q = 0; q < 4; q++) {
                int u = q*256 + tid;
                int cin = u >> 4, co4 = u & 15;
                pf[q] = w4[((size_t)(t+1)*64 + cin)*192 + (c0 >> 2) + co4];
            }
        }

        const float4* wt = (t & 1) ? wb1 : wb0;
        int ky = t / 3, kx = t - ky*3;
        int ib0 = ((oy + 2*ky)*20 + ox + 2*kx)*17;

        #pragma unroll
        for (int c4 = 0; c4 < 16; c4++) {
            float4 xv[8];
            #pragma unroll
            for (int i = 0; i < 8; i++)
                xv[i] = in4[ib0 + 680*i + c4];     // 680 = 2 rows * 20 pix * 17 f4
            #pragma unroll
            for (int cc = 0; cc < 4; cc++) {
                F4U2 wlo, whi;
                wlo.f = wt[(c4*4 + cc)*16 + cg*2];
                whi.f = wt[(c4*4 + cc)*16 + cg*2 + 1];
                #pragma unroll
                for (int i = 0; i < 8; i++) {
                    float a = ((const float*)&xv[i])[cc];
                    unsigned long long aa;
                    PACK_AA(aa, a);
                    FMA_F32X2(acc[i][0], aa, wlo.u[0]);
                    FMA_F32X2(acc[i][1], aa, wlo.u[1]);
                    FMA_F32X2(acc[i][2], aa, whi.u[0]);
                    FMA_F32X2(acc[i][3], aa, whi.u[1]);
                }
            }
        }

        // commit prefetched tap, then one sync per tap
        if (t < 8) {
            float4* wn = (t & 1) ? wb0 : wb1;
            #pragma unroll
            for (int q = 0; q < 4; q++) wn[q*256 + tid] = pf[q];
        }
        __syncthreads();
    }

    // ---- epilogue: +bias, ReLU, store NHWC ----
    float fc[8];
    #pragma unroll
    for (int j = 0; j < 8; j++) fc[j] = g_fconst[c0 + cg*8 + j];

    #pragma unroll
    for (int i = 0; i < 8; i++) {
        int y = ty*16 + oy + 2*i;
        int x = tx*16 + ox;
        size_t base = ((size_t)b*NPIX + (size_t)y*HWD + x)*EE + c0 + cg*8;
        float o[8];
        #pragma unroll
        for (int j = 0; j < 4; j++) {
            float lo, hi;
            UNPACK2(lo, hi, acc[i][j]);
            o[j*2]   = fmaxf(lo + fc[j*2],   0.f);
            o[j*2+1] = fmaxf(hi + fc[j*2+1], 0.f);
        }
        ((float4*)&g_feats[base])[0] = make_float4(o[0],o[1],o[2],o[3]);
        ((float4*)&g_feats[base])[1] = make_float4(o[4],o[5],o[6],o[7]);
    }
}

// ------------------------------------------------------------------
// per-(b,seg) mean/max pooling over pixel list; each thread owns 3 channels
__global__ void k_pool() {
    __shared__ int sp[256];
    int k = blockIdx.x;
    int b = k / MM;
    int tid = threadIdx.x;
    int cnt = g_cnt[k];
    int off = g_off[k];
    const float* fb = g_feats + (size_t)b*NPIX*EE;

    float s0=0.f, s1=0.f, s2=0.f, m0=0.f, m1=0.f, m2=0.f;
    for (int base = 0; base < cnt; base += 256) {
        int nchunk = min(256, cnt - base);
        __syncthreads();
        if (tid < nchunk) sp[tid] = g_plist[off + base + tid];
        __syncthreads();
        int i = 0;
        for (; i + 1 < nchunk; i += 2) {
            const float* f0 = fb + (size_t)sp[i]*EE + tid;
            const float* f1 = fb + (size_t)sp[i+1]*EE + tid;
            float a0 = f0[0], b0 = f0[256], c0v = f0[512];
            float a1 = f1[0], b1 = f1[256], c1v = f1[512];
            s0 += a0 + a1; s1 += b0 + b1; s2 += c0v + c1v;
            m0 = fmaxf(m0, fmaxf(a0, a1));
            m1 = fmaxf(m1, fmaxf(b0, b1));
            m2 = fmaxf(m2, fmaxf(c0v, c1v));
        }
        if (i < nchunk) {
            const float* f0 = fb + (size_t)sp[i]*EE + tid;
            float a0 = f0[0], b0 = f0[256], c0v = f0[512];
            s0 += a0; s1 += b0; s2 += c0v;
            m0 = fmaxf(m0, a0); m1 = fmaxf(m1, b0); m2 = fmaxf(m2, c0v);
        }
    }
    float n = fmaxf((float)cnt, 1.f);
    float* dst = g_concat + (size_t)k*1536;
    dst[tid]        = s0/n;  dst[256 + tid]  = s1/n;  dst[512 + tid]  = s2/n;
    dst[768 + tid]  = m0;    dst[1024 + tid] = m1;    dst[1280 + tid] = m2;
}

// ------------------------------------------------------------------
// fused = concat @ fusion_w^T + b, *W_k, + positional embedding
__global__ void k_fuse(const float* fw, const float* fbias, const float* pw,
                       const float* pb, const float* cent, float* out) {
    __shared__ float As[16][68];
    __shared__ float Bs[16][68];
    int tid = threadIdx.x;
    int d0 = blockIdx.x * 64;
    int r0 = blockIdx.y * 64;
    int tx = tid % 16, ty2 = tid / 16;

    float acc[4][4];
    #pragma unroll
    for (int i = 0; i < 4; i++)
        #pragma unroll
        for (int j = 0; j < 4; j++) acc[i][j] = 0.f;

    for (int kk = 0; kk < 2*EE; kk += 16) {
        {
            int ar = tid >> 2, ac4 = tid & 3;
            int r = r0 + ar;
            float4 v = make_float4(0.f,0.f,0.f,0.f);
            if (r < KK)
                v = ((const float4*)(g_concat + (size_t)r*1536 + kk))[ac4];
            As[ac4*4+0][ar] = v.x; As[ac4*4+1][ar] = v.y;
            As[ac4*4+2][ar] = v.z; As[ac4*4+3][ar] = v.w;
        }
        {
            int dd = tid >> 2, cc4 = tid & 3;
            float4 v = ((const float4*)(fw + (size_t)(d0 + dd)*1536 + kk))[cc4];
            Bs[cc4*4+0][dd] = v.x; Bs[cc4*4+1][dd] = v.y;
            Bs[cc4*4+2][dd] = v.z; Bs[cc4*4+3][dd] = v.w;
        }
        __syncthreads();
        #pragma unroll
        for (int q = 0; q < 16; q++) {
            float4 a = *(const float4*)&As[q][ty2*4];
            float4 bv = *(const float4*)&Bs[q][tx*4];
            const float* ap = (const float*)&a;
            const float* bp = (const float*)&bv;
            #pragma unroll
            for (int i = 0; i < 4; i++)
                #pragma unroll
                for (int j = 0; j < 4; j++)
                    acc[i][j] += ap[i] * bp[j];
        }
        __syncthreads();
    }

    #pragma unroll
    for (int i = 0; i < 4; i++) {
        int r = r0 + ty2*4 + i;
        if (r >= KK) continue;
        float wk = g_wk[r];
        float cx = __ldg(&cent[r*2 + 0]) * (1.f/224.f);
        float cy = __ldg(&cent[r*2 + 1]) * (1.f/224.f);
        #pragma unroll
        for (int j = 0; j < 4; j++) {
            int d = d0 + tx*4 + j;
            float v = (acc[i][j] + __ldg(&fbias[d])) * wk;
            v += cx*__ldg(&pw[d*2 + 0]) + cy*__ldg(&pw[d*2 + 1]) + __ldg(&pb[d]);
            out[(size_t)r*EE + d] = v;
        }
    }
}

// ------------------------------------------------------------------
extern "C" void kernel_launch(void* const* d_in, const int* in_sizes, int n_in,
                              void* d_out, int out_size) {
    const float* img   = (const float*)d_in[0];
    const int*   seg   = (const int*)d_in[1];
    const float* cent  = (const float*)d_in[2];
    const float* c1w   = (const float*)d_in[3];
    const float* c1b   = (const float*)d_in[4];
    const float* bn1g  = (const float*)d_in[5];
    const float* bn1b  = (const float*)d_in[6];
    const float* bn1m  = (const float*)d_in[7];
    const float* bn1v  = (const float*)d_in[8];
    const float* c2w   = (const float*)d_in[9];
    const float* c2b   = (const float*)d_in[10];
    const float* bn2g  = (const float*)d_in[11];
    const float* bn2b  = (const float*)d_in[12];
    const float* bn2m  = (const float*)d_in[13];
    const float* bn2v  = (const float*)d_in[14];
    const float* edgew = (const float*)d_in[15];
    const float* posw  = (const float*)d_in[16];
    const float* posb  = (const float*)d_in[17];
    const float* fusw  = (const float*)d_in[18];
    const float* fusb  = (const float*)d_in[19];
    float* out = (float*)d_out;
    (void)n_in; (void)in_sizes;

    const int FINAL_N = BB*MM*EE;          // 301056
    int goff = (out_size >= FINAL_N + BB*NPIX)   ? FINAL_N : -1;
    int soff = (out_size >= FINAL_N + 2*BB*NPIX) ? FINAL_N + BB*NPIX : -1;

    cudaFuncSetAttribute(k_conv2, cudaFuncAttributeMaxDynamicSharedMemorySize, SMEM2_B);

    k_zero<<<1024, 256>>>();
    k_prep_fconst<<<1, EE>>>(c2b, bn2g, bn2b, bn2m, bn2v);
    k_prep_w2t<<<(9*C1*EE + 255)/256, 256>>>(c2w, bn2g, bn2v);
    k_conv1<<<(BB*NPIX*8)/256, 256>>>(img, c1w, c1b, bn1g, bn1b, bn1m, bn1v);
    k_edge<<<BB*NPIX/256, 256>>>(img, seg, edgew, out, goff, soff);
    k_scan<<<1, 512>>>();
    k_scatter<<<BB*NPIX/256, 256>>>(seg);
    k_conv2<<<dim3(196, 12, BB), 256, SMEM2_B>>>();
    k_pool<<<KK, 256>>>();
    k_fuse<<<dim3(EE/64, (KK + 63)/64), 256>>>(fusw, fusb, posw, posb, cent, out);
}

// round 9
// speedup vs baseline: 1.7239x; 1.6126x over previous
#include <cuda_runtime.h>
#include <cuda_bf16.h>
#include <mma.h>
#include <cstdint>

using namespace nvcuda;

#define HWD   224
#define NPIX  (HWD*HWD)        // 50176
#define BB    2
#define C1    64
#define EE    768
#define MM    196
#define KK    (BB*MM)          // 392
#define PADW  228
#define BNEPS 1e-5f

// ---- static device scratch (no allocation allowed) ----
__device__ __nv_bfloat16 g_xh[(size_t)BB*PADW*PADW*C1];   // conv1 out hi (bf16, padded NHWC)
__device__ __nv_bfloat16 g_xl[(size_t)BB*PADW*PADW*C1];   // conv1 out lo
__device__ __nv_bfloat16 g_wbh[9*EE*C1];                  // conv2 w hi: [t][cout][cin], BN-folded
__device__ __nv_bfloat16 g_wbl[9*EE*C1];                  // conv2 w lo
__device__ float g_feats[77070336];                       // conv2 out NHWC [B][HW][E]
__device__ float g_fconst[EE];
__device__ int   g_cnt[KK];
__device__ float g_sim[KK];
__device__ float g_wk[KK];
__device__ int   g_off[KK+1];
__device__ int   g_cur[KK];
__device__ int   g_plist[BB*NPIX];
__device__ float g_concat[KK*2*EE];

// ------------------------------------------------------------------
__global__ void k_zero() {
    float4* ph = (float4*)g_xh;    // 8 bf16 per float4
    float4* pl = (float4*)g_xl;
    const int n4 = ((size_t)BB*PADW*PADW*C1)/8;
    for (int i = blockIdx.x*blockDim.x + threadIdx.x; i < n4; i += gridDim.x*blockDim.x) {
        ph[i] = make_float4(0.f,0.f,0.f,0.f);
        pl[i] = make_float4(0.f,0.f,0.f,0.f);
    }
    if (blockIdx.x == 0) {
        for (int i = threadIdx.x; i < KK; i += blockDim.x) {
            g_cnt[i] = 0; g_sim[i] = 0.f; g_cur[i] = 0;
        }
    }
}

// ------------------------------------------------------------------
__global__ void k_prep_fconst(const float* cb, const float* bg, const float* bb_,
                              const float* bm, const float* bv) {
    int c = threadIdx.x;
    if (c < EE) {
        float inv = bg[c] * rsqrtf(bv[c] + BNEPS);
        g_fconst[c] = cb[c]*inv + bb_[c] - bm[c]*inv;
    }
}

// conv2 weights -> [t][cout][cin] bf16 hi/lo, BN-folded
__global__ void k_prep_wb(const float* w, const float* bg, const float* bv) {
    int i = blockIdx.x*blockDim.x + threadIdx.x;
    const int n = 9*EE*C1;
    if (i < n) {
        int cin  = i & 63;
        int r    = i >> 6;
        int cout = r % EE;
        int t    = r / EE;
        float inv = __ldg(&bg[cout]) * rsqrtf(__ldg(&bv[cout]) + BNEPS);
        float v = __ldg(&w[cout*(C1*9) + cin*9 + t]) * inv;
        __nv_bfloat16 h = __float2bfloat16(v);
        __nv_bfloat16 l = __float2bfloat16(v - __bfloat162float(h));
        g_wbh[i] = h; g_wbl[i] = l;
    }
}

// ------------------------------------------------------------------
// conv1 3->64, 3x3 pad1 + BN + ReLU, emit bf16 hi/lo into padded buffers
__global__ void k_conv1(const float* img, const float* w, const float* bias,
                        const float* bg, const float* bb_, const float* bm, const float* bv) {
    int gid = blockIdx.x*blockDim.x + threadIdx.x;
    int cg  = gid & 7;
    int pix = gid >> 3;
    if (pix >= BB*NPIX) return;
    int b = pix / NPIX, p = pix % NPIX;
    int y = p / HWD, x = p % HWD;

    float in[27];
    #pragma unroll
    for (int ci = 0; ci < 3; ci++)
        #pragma unroll
        for (int ky = 0; ky < 3; ky++)
            #pragma unroll
            for (int kx = 0; kx < 3; kx++) {
                int yy = y + ky - 1, xx = x + kx - 1;
                float v = 0.f;
                if (yy >= 0 && yy < HWD && xx >= 0 && xx < HWD)
                    v = __ldg(&img[((b*3 + ci)*HWD + yy)*HWD + xx]);
                in[ci*9 + ky*3 + kx] = v;
            }
    int c0 = cg*8;
    __nv_bfloat16 hh[8], ll[8];
    #pragma unroll
    for (int j = 0; j < 8; j++) {
        int c = c0 + j;
        float acc = 0.f;
        #pragma unroll
        for (int q = 0; q < 27; q++) acc += in[q] * __ldg(&w[c*27 + q]);
        float inv = __ldg(&bg[c]) * rsqrtf(__ldg(&bv[c]) + BNEPS);
        float v = (acc + __ldg(&bias[c]))*inv + __ldg(&bb_[c]) - __ldg(&bm[c])*inv;
        v = fmaxf(v, 0.f);
        hh[j] = __float2bfloat16(v);
        ll[j] = __float2bfloat16(v - __bfloat162float(hh[j]));
    }
    size_t base = (((size_t)b*PADW + y + 2)*PADW + x + 2)*C1 + c0;
    *(uint4*)&g_xh[base] = *(uint4*)hh;
    *(uint4*)&g_xl[base] = *(uint4*)ll;
}

// ------------------------------------------------------------------
__global__ void k_edge(const float* img, const int* seg, const float* ew,
                       float* out, int goff, int soff) {
    __shared__ int   scnt[MM];
    __shared__ float ssim[MM];
    int tid = threadIdx.x;
    if (tid < MM) { scnt[tid] = 0; ssim[tid] = 0.f; }
    __syncthreads();

    int gid = blockIdx.x*256 + tid;
    int b = gid / NPIX, p = gid % NPIX;
    int y = p / HWD, x = p % HWD;

    float e0 = 0.f, e1 = 0.f;
    #pragma unroll
    for (int ky = 0; ky < 3; ky++)
        #pragma unroll
        for (int kx = 0; kx < 3; kx++) {
            int yy = y + ky - 1, xx = x + kx - 1;
            float gr = 0.f;
            if (yy >= 0 && yy < HWD && xx >= 0 && xx < HWD) {
                int base = (b*3*HWD + yy)*HWD + xx;
                gr = (__ldg(&img[base]) + __ldg(&img[base + NPIX]) + __ldg(&img[base + 2*NPIX])) * (1.f/3.f);
            }
            e0 += gr * __ldg(&ew[ky*3 + kx]);
            e1 += gr * __ldg(&ew[9 + ky*3 + kx]);
        }
    float grad = sqrtf(e0*e0 + e1*e1 + 1e-8f);
    float sim  = fminf(fmaxf(1.f - grad, 0.f), 1.f);
    int s = seg[gid];
    if (goff >= 0) out[goff + gid] = grad;
    if (soff >= 0) out[soff + gid] = (float)s;
    atomicAdd(&scnt[s], 1);
    atomicAdd(&ssim[s], sim);
    __syncthreads();
    if (tid < MM) {
        if (scnt[tid]) atomicAdd(&g_cnt[b*MM + tid], scnt[tid]);
        if (ssim[tid] != 0.f) atomicAdd(&g_sim[b*MM + tid], ssim[tid]);
    }
}

// ------------------------------------------------------------------
__global__ void k_scan() {
    __shared__ int s[512];
    int tid = threadIdx.x;
    int v = (tid < KK) ? g_cnt[tid] : 0;
    s[tid] = v;
    __syncthreads();
    for (int d = 1; d < 512; d <<= 1) {
        int t = (tid >= d) ? s[tid - d] : 0;
        __syncthreads();
        s[tid] += t;
        __syncthreads();
    }
    if (tid < KK) {
        g_off[tid] = s[tid] - v;
        g_wk[tid]  = g_sim[tid] / fmaxf((float)v, 1.f);
    }
    if (tid == 0) g_off[KK] = s[511];
}

__global__ void k_scatter(const int* seg) {
    int gid = blockIdx.x*256 + threadIdx.x;
    int b = gid / NPIX, p = gid % NPIX;
    int k = b*MM + seg[gid];
    int pos = atomicAdd(&g_cur[k], 1);
    g_plist[g_off[k] + pos] = p;
}

// ------------------------------------------------------------------
// conv2 via WMMA (legacy HMMA): block = 64 px x 128 cout,
// split-bf16 3 terms (xh*wh + xl*wh + xh*wl), fp32 accumulate.
// 8 warps; warp w: m_tile = w&3 (16 px), n_tiles = (w>>2)*4 .. +3 (4 x 16 cout).
#define LDA 72
#define LDB 72
#define OFF_AH 0
#define OFF_AL (64*LDA)              // elems
#define OFF_BH (2*64*LDA)
#define OFF_BL (2*64*LDA + 128*LDB)
#define SMEM_W ((2*64*LDA + 2*128*LDB)*2)   // 55296 bytes

__global__ void __launch_bounds__(256) k_conv2_wmma() {
    extern __shared__ __nv_bfloat16 sm[];
    int tid = threadIdx.x, wid = tid >> 5;
    int p0 = blockIdx.x * 64;
    int c0 = blockIdx.y * 128;
    int b  = blockIdx.z;

    int m_tile = wid & 3;
    int n_base = (wid >> 2) * 4;

    wmma::fragment<wmma::accumulator, 16, 16, 16, float> acc[4];
    #pragma unroll
    for (int i = 0; i < 4; i++) wmma::fill_fragment(acc[i], 0.f);

    #pragma unroll 1
    for (int t = 0; t < 9; t++) {
        int ky = t / 3, kx = t - ky*3;
        // ---- stage A: 64 px x 64 cin, hi+lo (2*64*8 = 1024 uint4) ----
        #pragma unroll
        for (int q = 0; q < 4; q++) {
            int u = q*256 + tid;              // 0..1023
            int term = u >> 9;
            int v    = u & 511;
            int px   = v >> 3, c8 = v & 7;
            int p = p0 + px;
            int y = p / HWD, x = p - y*HWD;
            const __nv_bfloat16* src = (term ? g_xl : g_xh)
                + (((size_t)b*PADW + y + 2*ky)*PADW + (x + 2*kx))*C1;
            uint4 val = *((const uint4*)src + c8);
            *(uint4*)&sm[(term ? OFF_AL : OFF_AH) + px*LDA + c8*8] = val;
        }
        // ---- stage B: 128 cout x 64 cin, hi+lo (2*128*8 = 2048 uint4) ----
        #pragma unroll
        for (int q = 0; q < 8; q++) {
            int u = q*256 + tid;              // 0..2047   (FIX: was 0..1023)
            int term = u >> 10;
            int v    = u & 1023;
            int co   = v >> 3, c8 = v & 7;    // co 0..127
            const __nv_bfloat16* src = (term ? g_wbl : g_wbh)
                + ((size_t)t*EE + c0 + co)*C1;
            uint4 val = *((const uint4*)src + c8);
            *(uint4*)&sm[(term ? OFF_BL : OFF_BH) + co*LDB + c8*8] = val;
        }
        __syncthreads();

        #pragma unroll
        for (int kc = 0; kc < 4; kc++) {
            wmma::fragment<wmma::matrix_a, 16, 16, 16, __nv_bfloat16, wmma::row_major> ah, al;
            wmma::load_matrix_sync(ah, &sm[OFF_AH + m_tile*16*LDA + kc*16], LDA);
            wmma::load_matrix_sync(al, &sm[OFF_AL + m_tile*16*LDA + kc*16], LDA);
            #pragma unroll
            for (int nt = 0; nt < 4; nt++) {
                int n_tile = n_base + nt;
                wmma::fragment<wmma::matrix_b, 16, 16, 16, __nv_bfloat16, wmma::col_major> bh, bl;
                wmma::load_matrix_sync(bh, &sm[OFF_BH + n_tile*16*LDB + kc*16], LDB);
                wmma::load_matrix_sync(bl, &sm[OFF_BL + n_tile*16*LDB + kc*16], LDB);
                wmma::mma_sync(acc[nt], ah, bh, acc[nt]);
                wmma::mma_sync(acc[nt], al, bh, acc[nt]);
                wmma::mma_sync(acc[nt], ah, bl, acc[nt]);
            }
        }
        __syncthreads();
    }

    // ---- epilogue: frags -> smem (fp32) -> bias+ReLU -> gmem ----
    float* cs = (float*)sm;      // 64 x 128 floats = 32KB, fits
    #pragma unroll
    for (int nt = 0; nt < 4; nt++)
        wmma::store_matrix_sync(cs + (m_tile*16)*128 + (n_base + nt)*16, acc[nt],
                                128, wmma::mem_row_major);
    __syncthreads();

    #pragma unroll
    for (int q = 0; q < 8; q++) {
        int u = q*256 + tid;             // float4 index, 0..2047
        int row = u >> 5, col4 = u & 31;
        float4 v = ((const float4*)cs)[u];
        int cb = c0 + col4*4;
        v.x = fmaxf(v.x + __ldg(&g_fconst[cb+0]), 0.f);
        v.y = fmaxf(v.y + __ldg(&g_fconst[cb+1]), 0.f);
        v.z = fmaxf(v.z + __ldg(&g_fconst[cb+2]), 0.f);
        v.w = fmaxf(v.w + __ldg(&g_fconst[cb+3]), 0.f);
        *(float4*)&g_feats[((size_t)b*NPIX + p0 + row)*EE + cb] = v;
    }
}

// ------------------------------------------------------------------
// per-(b,seg) mean/max pooling over pixel list; each thread owns 3 channels
__global__ void k_pool() {
    __shared__ int sp[256];
    int k = blockIdx.x;
    int b = k / MM;
    int tid = threadIdx.x;
    int cnt = g_cnt[k];
    int off = g_off[k];
    const float* fb = g_feats + (size_t)b*NPIX*EE;

    float s0=0.f, s1=0.f, s2=0.f, m0=0.f, m1=0.f, m2=0.f;
    for (int base = 0; base < cnt; base += 256) {
        int nchunk = min(256, cnt - base);
        __syncthreads();
        if (tid < nchunk) sp[tid] = g_plist[off + base + tid];
        __syncthreads();
        int i = 0;
        for (; i + 1 < nchunk; i += 2) {
            const float* f0 = fb + (size_t)sp[i]*EE + tid;
            const float* f1 = fb + (size_t)sp[i+1]*EE + tid;
            float a0 = f0[0], b0 = f0[256], c0v = f0[512];
            float a1 = f1[0], b1 = f1[256], c1v = f1[512];
            s0 += a0 + a1; s1 += b0 + b1; s2 += c0v + c1v;
            m0 = fmaxf(m0, fmaxf(a0, a1));
            m1 = fmaxf(m1, fmaxf(b0, b1));
            m2 = fmaxf(m2, fmaxf(c0v, c1v));
        }
        if (i < nchunk) {
            const float* f0 = fb + (size_t)sp[i]*EE + tid;
            float a0 = f0[0], b0 = f0[256], c0v = f0[512];
            s0 += a0; s1 += b0; s2 += c0v;
            m0 = fmaxf(m0, a0); m1 = fmaxf(m1, b0); m2 = fmaxf(m2, c0v);
        }
    }
    float n = fmaxf((float)cnt, 1.f);
    float* dst = g_concat + (size_t)k*1536;
    dst[tid]        = s0/n;  dst[256 + tid]  = s1/n;  dst[512 + tid]  = s2/n;
    dst[768 + tid]  = m0;    dst[1024 + tid] = m1;    dst[1280 + tid] = m2;
}

// ------------------------------------------------------------------
// fused = concat @ fusion_w^T + b, *W_k, + positional embedding
__global__ void k_fuse(const float* fw, const float* fbias, const float* pw,
                       const float* pb, const float* cent, float* out) {
    __shared__ float As[16][68];
    __shared__ float Bs[16][68];
    int tid = threadIdx.x;
    int d0 = blockIdx.x * 64;
    int r0 = blockIdx.y * 64;
    int tx = tid % 16, ty2 = tid / 16;

    float acc[4][4];
    #pragma unroll
    for (int i = 0; i < 4; i++)
        #pragma unroll
        for (int j = 0; j < 4; j++) acc[i][j] = 0.f;

    for (int kk = 0; kk < 2*EE; kk += 16) {
        {
            int ar = tid >> 2, ac4 = tid & 3;
            int r = r0 + ar;
            float4 v = make_float4(0.f,0.f,0.f,0.f);
            if (r < KK)
                v = ((const float4*)(g_concat + (size_t)r*1536 + kk))[ac4];
            As[ac4*4+0][ar] = v.x; As[ac4*4+1][ar] = v.y;
            As[ac4*4+2][ar] = v.z; As[ac4*4+3][ar] = v.w;
        }
        {
            int dd = tid >> 2, cc4 = tid & 3;
            float4 v = ((const float4*)(fw + (size_t)(d0 + dd)*1536 + kk))[cc4];
            Bs[cc4*4+0][dd] = v.x; Bs[cc4*4+1][dd] = v.y;
            Bs[cc4*4+2][dd] = v.z; Bs[cc4*4+3][dd] = v.w;
        }
        __syncthreads();
        #pragma unroll
        for (int q = 0; q < 16; q++) {
            float4 a = *(const float4*)&As[q][ty2*4];
            float4 bv = *(const float4*)&Bs[q][tx*4];
            const float* ap = (const float*)&a;
            const float* bp = (const float*)&bv;
            #pragma unroll
            for (int i = 0; i < 4; i++)
                #pragma unroll
                for (int j = 0; j < 4; j++)
                    acc[i][j] += ap[i] * bp[j];
        }
        __syncthreads();
    }

    #pragma unroll
    for (int i = 0; i < 4; i++) {
        int r = r0 + ty2*4 + i;
        if (r >= KK) continue;
        float wk = g_wk[r];
        float cx = __ldg(&cent[r*2 + 0]) * (1.f/224.f);
        float cy = __ldg(&cent[r*2 + 1]) * (1.f/224.f);
        #pragma unroll
        for (int j = 0; j < 4; j++) {
            int d = d0 + tx*4 + j;
            float v = (acc[i][j] + __ldg(&fbias[d])) * wk;
            v += cx*__ldg(&pw[d*2 + 0]) + cy*__ldg(&pw[d*2 + 1]) + __ldg(&pb[d]);
            out[(size_t)r*EE + d] = v;
        }
    }
}

// ------------------------------------------------------------------
extern "C" void kernel_launch(void* const* d_in, const int* in_sizes, int n_in,
                              void* d_out, int out_size) {
    const float* img   = (const float*)d_in[0];
    const int*   seg   = (const int*)d_in[1];
    const float* cent  = (const float*)d_in[2];
    const float* c1w   = (const float*)d_in[3];
    const float* c1b   = (const float*)d_in[4];
    const float* bn1g  = (const float*)d_in[5];
    const float* bn1b  = (const float*)d_in[6];
    const float* bn1m  = (const float*)d_in[7];
    const float* bn1v  = (const float*)d_in[8];
    const float* c2w   = (const float*)d_in[9];
    const float* c2b   = (const float*)d_in[10];
    const float* bn2g  = (const float*)d_in[11];
    const float* bn2b  = (const float*)d_in[12];
    const float* bn2m  = (const float*)d_in[13];
    const float* bn2v  = (const float*)d_in[14];
    const float* edgew = (const float*)d_in[15];
    const float* posw  = (const float*)d_in[16];
    const float* posb  = (const float*)d_in[17];
    const float* fusw  = (const float*)d_in[18];
    const float* fusb  = (const float*)d_in[19];
    float* out = (float*)d_out;
    (void)n_in; (void)in_sizes;

    const int FINAL_N = BB*MM*EE;
    int goff = (out_size >= FINAL_N + BB*NPIX)   ? FINAL_N : -1;
    int soff = (out_size >= FINAL_N + 2*BB*NPIX) ? FINAL_N + BB*NPIX : -1;

    cudaFuncSetAttribute(k_conv2_wmma, cudaFuncAttributeMaxDynamicSharedMemorySize, SMEM_W);

    k_zero<<<1024, 256>>>();
    k_prep_fconst<<<1, EE>>>(c2b, bn2g, bn2b, bn2m, bn2v);
    k_prep_wb<<<(9*EE*C1 + 255)/256, 256>>>(c2w, bn2g, bn2v);
    k_conv1<<<(BB*NPIX*8)/256, 256>>>(img, c1w, c1b, bn1g, bn1b, bn1m, bn1v);
    k_edge<<<BB*NPIX/256, 256>>>(img, seg, edgew, out, goff, soff);
    k_scan<<<1, 512>>>();
    k_scatter<<<BB*NPIX/256, 256>>>(seg);
    k_conv2_wmma<<<dim3(NPIX/64, EE/128, BB), 256, SMEM_W>>>();
    k_pool<<<KK, 256>>>();
    k_fuse<<<dim3(EE/64, (KK + 63)/64), 256>>>(fusw, fusb, posw, posb, cent, out);
}

// round 11
// speedup vs baseline: 1.8644x; 1.0815x over previous
#include <cuda_runtime.h>
#include <cuda_bf16.h>
#include <mma.h>
#include <cstdint>

using namespace nvcuda;

#define HWD   224
#define NPIX  (HWD*HWD)        // 50176
#define BB    2
#define C1    64
#define EE    768
#define MM    196
#define KK    (BB*MM)          // 392
#define PADW  228
#define BNEPS 1e-5f

// ---- static device scratch (no allocation allowed) ----
__device__ __nv_bfloat16 g_xh[(size_t)BB*PADW*PADW*C1];   // conv1 out hi (bf16, padded NHWC)
__device__ __nv_bfloat16 g_xl[(size_t)BB*PADW*PADW*C1];   // conv1 out lo
__device__ __nv_bfloat16 g_wbh[9*EE*C1];                  // conv2 w hi: [t][cout][cin], BN-folded
__device__ __nv_bfloat16 g_wbl[9*EE*C1];                  // conv2 w lo
__device__ float g_feats[77070336];                       // conv2 out NHWC [B][HW][E]
__device__ float g_fconst[EE];
__device__ int   g_cnt[KK];
__device__ float g_sim[KK];
__device__ float g_wk[KK];
__device__ int   g_off[KK+1];
__device__ int   g_cur[KK];
__device__ int   g_plist[BB*NPIX];
__device__ float g_concat[KK*2*EE];

// ------------------------------------------------------------------
__global__ void k_zero() {
    float4* ph = (float4*)g_xh;    // 8 bf16 per float4
    float4* pl = (float4*)g_xl;
    const int n4 = ((size_t)BB*PADW*PADW*C1)/8;
    for (int i = blockIdx.x*blockDim.x + threadIdx.x; i < n4; i += gridDim.x*blockDim.x) {
        ph[i] = make_float4(0.f,0.f,0.f,0.f);
        pl[i] = make_float4(0.f,0.f,0.f,0.f);
    }
    if (blockIdx.x == 0) {
        for (int i = threadIdx.x; i < KK; i += blockDim.x) {
            g_cnt[i] = 0; g_sim[i] = 0.f; g_cur[i] = 0;
        }
    }
}

// ------------------------------------------------------------------
__global__ void k_prep_fconst(const float* cb, const float* bg, const float* bb_,
                              const float* bm, const float* bv) {
    int c = threadIdx.x;
    if (c < EE) {
        float inv = bg[c] * rsqrtf(bv[c] + BNEPS);
        g_fconst[c] = cb[c]*inv + bb_[c] - bm[c]*inv;
    }
}

// conv2 weights -> [t][cout][cin] bf16 hi/lo, BN-folded
__global__ void k_prep_wb(const float* w, const float* bg, const float* bv) {
    int i = blockIdx.x*blockDim.x + threadIdx.x;
    const int n = 9*EE*C1;
    if (i < n) {
        int cin  = i & 63;
        int r    = i >> 6;
        int cout = r % EE;
        int t    = r / EE;
        float inv = __ldg(&bg[cout]) * rsqrtf(__ldg(&bv[cout]) + BNEPS);
        float v = __ldg(&w[cout*(C1*9) + cin*9 + t]) * inv;
        __nv_bfloat16 h = __float2bfloat16(v);
        __nv_bfloat16 l = __float2bfloat16(v - __bfloat162float(h));
        g_wbh[i] = h; g_wbl[i] = l;
    }
}

// ------------------------------------------------------------------
// conv1 3->64, 3x3 pad1 + BN + ReLU, emit bf16 hi/lo into padded buffers
__global__ void k_conv1(const float* img, const float* w, const float* bias,
                        const float* bg, const float* bb_, const float* bm, const float* bv) {
    int gid = blockIdx.x*blockDim.x + threadIdx.x;
    int cg  = gid & 7;
    int pix = gid >> 3;
    if (pix >= BB*NPIX) return;
    int b = pix / NPIX, p = pix % NPIX;
    int y = p / HWD, x = p % HWD;

    float in[27];
    #pragma unroll
    for (int ci = 0; ci < 3; ci++)
        #pragma unroll
        for (int ky = 0; ky < 3; ky++)
            #pragma unroll
            for (int kx = 0; kx < 3; kx++) {
                int yy = y + ky - 1, xx = x + kx - 1;
                float v = 0.f;
                if (yy >= 0 && yy < HWD && xx >= 0 && xx < HWD)
                    v = __ldg(&img[((b*3 + ci)*HWD + yy)*HWD + xx]);
                in[ci*9 + ky*3 + kx] = v;
            }
    int c0 = cg*8;
    __nv_bfloat16 hh[8], ll[8];
    #pragma unroll
    for (int j = 0; j < 8; j++) {
        int c = c0 + j;
        float acc = 0.f;
        #pragma unroll
        for (int q = 0; q < 27; q++) acc += in[q] * __ldg(&w[c*27 + q]);
        float inv = __ldg(&bg[c]) * rsqrtf(__ldg(&bv[c]) + BNEPS);
        float v = (acc + __ldg(&bias[c]))*inv + __ldg(&bb_[c]) - __ldg(&bm[c])*inv;
        v = fmaxf(v, 0.f);
        hh[j] = __float2bfloat16(v);
        ll[j] = __float2bfloat16(v - __bfloat162float(hh[j]));
    }
    size_t base = (((size_t)b*PADW + y + 2)*PADW + x + 2)*C1 + c0;
    *(uint4*)&g_xh[base] = *(uint4*)hh;
    *(uint4*)&g_xl[base] = *(uint4*)ll;
}

// ------------------------------------------------------------------
__global__ void k_edge(const float* img, const int* seg, const float* ew,
                       float* out, int goff, int soff) {
    __shared__ int   scnt[MM];
    __shared__ float ssim[MM];
    int tid = threadIdx.x;
    if (tid < MM) { scnt[tid] = 0; ssim[tid] = 0.f; }
    __syncthreads();

    int gid = blockIdx.x*256 + tid;
    int b = gid / NPIX, p = gid % NPIX;
    int y = p / HWD, x = p % HWD;

    float e0 = 0.f, e1 = 0.f;
    #pragma unroll
    for (int ky = 0; ky < 3; ky++)
        #pragma unroll
        for (int kx = 0; kx < 3; kx++) {
            int yy = y + ky - 1, xx = x + kx - 1;
            float gr = 0.f;
            if (yy >= 0 && yy < HWD && xx >= 0 && xx < HWD) {
                int base = (b*3*HWD + yy)*HWD + xx;
                gr = (__ldg(&img[base]) + __ldg(&img[base + NPIX]) + __ldg(&img[base + 2*NPIX])) * (1.f/3.f);
            }
            e0 += gr * __ldg(&ew[ky*3 + kx]);
            e1 += gr * __ldg(&ew[9 + ky*3 + kx]);
        }
    float grad = sqrtf(e0*e0 + e1*e1 + 1e-8f);
    float sim  = fminf(fmaxf(1.f - grad, 0.f), 1.f);
    int s = seg[gid];
    if (goff >= 0) out[goff + gid] = grad;
    if (soff >= 0) out[soff + gid] = (float)s;
    atomicAdd(&scnt[s], 1);
    atomicAdd(&ssim[s], sim);
    __syncthreads();
    if (tid < MM) {
        if (scnt[tid]) atomicAdd(&g_cnt[b*MM + tid], scnt[tid]);
        if (ssim[tid] != 0.f) atomicAdd(&g_sim[b*MM + tid], ssim[tid]);
    }
}

// ------------------------------------------------------------------
__global__ void k_scan() {
    __shared__ int s[512];
    int tid = threadIdx.x;
    int v = (tid < KK) ? g_cnt[tid] : 0;
    s[tid] = v;
    __syncthreads();
    for (int d = 1; d < 512; d <<= 1) {
        int t = (tid >= d) ? s[tid - d] : 0;
        __syncthreads();
        s[tid] += t;
        __syncthreads();
    }
    if (tid < KK) {
        g_off[tid] = s[tid] - v;
        g_wk[tid]  = g_sim[tid] / fmaxf((float)v, 1.f);
    }
    if (tid == 0) g_off[KK] = s[511];
}

__global__ void k_scatter(const int* seg) {
    int gid = blockIdx.x*256 + threadIdx.x;
    int b = gid / NPIX, p = gid % NPIX;
    int k = b*MM + seg[gid];
    int pos = atomicAdd(&g_cur[k], 1);
    g_plist[g_off[k] + pos] = p;
}

// ------------------------------------------------------------------
// conv2 via WMMA (legacy HMMA): block = 128 px x 128 cout, 8 warps,
// warp = 32 px x 64 cout (2 m-tiles x 4 n-tiles).
// split-bf16 3 terms (xh*wh + xl*wh + xh*wl), fp32 accumulate.
#define LDA 72
#define OFF_AH 0
#define OFF_AL (128*LDA)             // elems
#define OFF_BH (2*128*LDA)
#define OFF_BL (3*128*LDA)
#define SMEM_W (4*128*LDA*2)         // 73728 bytes

__global__ void __launch_bounds__(256) k_conv2_wmma() {
    extern __shared__ __nv_bfloat16 sm[];
    int tid = threadIdx.x, wid = tid >> 5;
    int p0 = blockIdx.x * 128;
    int c0 = blockIdx.y * 128;
    int b  = blockIdx.z;

    int wm = wid & 3;            // m group: pixels wm*32 .. wm*32+31 (2 tiles)
    int wn = wid >> 2;           // n group: couts wn*64 .. wn*64+63 (4 tiles)

    wmma::fragment<wmma::accumulator, 16, 16, 16, float> acc[2][4];
    #pragma unroll
    for (int i = 0; i < 2; i++)
        #pragma unroll
        for (int j = 0; j < 4; j++) wmma::fill_fragment(acc[i][j], 0.f);

    #pragma unroll 1
    for (int t = 0; t < 9; t++) {
        int ky = t / 3, kx = t - ky*3;
        // ---- stage A: 128 px x 64 cin, hi+lo (2*128*8 = 2048 uint4) ----
        #pragma unroll
        for (int q = 0; q < 8; q++) {
            int u = q*256 + tid;              // 0..2047
            int term = u >> 10;
            int v    = u & 1023;
            int px   = v >> 3, c8 = v & 7;
            int p = p0 + px;
            int y = p / HWD, x = p - y*HWD;
            const __nv_bfloat16* src = (term ? g_xl : g_xh)
                + (((size_t)b*PADW + y + 2*ky)*PADW + (x + 2*kx))*C1;
            uint4 val = *((const uint4*)src + c8);
            *(uint4*)&sm[(term ? OFF_AL : OFF_AH) + px*LDA + c8*8] = val;
        }
        // ---- stage B: 128 cout x 64 cin, hi+lo (2*128*8 = 2048 uint4) ----
        #pragma unroll
        for (int q = 0; q < 8; q++) {
            int u = q*256 + tid;              // 0..2047
            int term = u >> 10;
            int v    = u & 1023;
            int co   = v >> 3, c8 = v & 7;    // co 0..127
            const __nv_bfloat16* src = (term ? g_wbl : g_wbh)
                + ((size_t)t*EE + c0 + co)*C1;
            uint4 val = *((const uint4*)src + c8);
            *(uint4*)&sm[(term ? OFF_BL : OFF_BH) + co*LDA + c8*8] = val;
        }
        __syncthreads();

        #pragma unroll
        for (int kc = 0; kc < 4; kc++) {
            wmma::fragment<wmma::matrix_a, 16, 16, 16, __nv_bfloat16, wmma::row_major> ah[2], al[2];
            #pragma unroll
            for (int i = 0; i < 2; i++) {
                int mrow = wm*32 + i*16;
                wmma::load_matrix_sync(ah[i], &sm[OFF_AH + mrow*LDA + kc*16], LDA);
                wmma::load_matrix_sync(al[i], &sm[OFF_AL + mrow*LDA + kc*16], LDA);
            }
            #pragma unroll
            for (int j = 0; j < 4; j++) {
                int nrow = wn*64 + j*16;
                wmma::fragment<wmma::matrix_b, 16, 16, 16, __nv_bfloat16, wmma::col_major> bh, bl;
                wmma::load_matrix_sync(bh, &sm[OFF_BH + nrow*LDA + kc*16], LDA);
                wmma::load_matrix_sync(bl, &sm[OFF_BL + nrow*LDA + kc*16], LDA);
                #pragma unroll
                for (int i = 0; i < 2; i++) {
                    wmma::mma_sync(acc[i][j], ah[i], bh, acc[i][j]);
                    wmma::mma_sync(acc[i][j], al[i], bh, acc[i][j]);
                    wmma::mma_sync(acc[i][j], ah[i], bl, acc[i][j]);
                }
            }
        }
        __syncthreads();
    }

    // ---- epilogue: frags -> smem (fp32) -> bias+ReLU -> gmem ----
    float* cs = (float*)sm;      // 128 x 128 floats = 64KB, fits in 72KB
    #pragma unroll
    for (int i = 0; i < 2; i++)
        #pragma unroll
        for (int j = 0; j < 4; j++)
            wmma::store_matrix_sync(cs + (wm*32 + i*16)*128 + wn*64 + j*16, acc[i][j],
                                    128, wmma::mem_row_major);
    __syncthreads();

    #pragma unroll
    for (int q = 0; q < 16; q++) {
        int u = q*256 + tid;             // float4 index, 0..4095
        int row = u >> 5, col4 = u & 31;
        float4 v = ((const float4*)cs)[u];
        int cb = c0 + col4*4;
        v.x = fmaxf(v.x + __ldg(&g_fconst[cb+0]), 0.f);
        v.y = fmaxf(v.y + __ldg(&g_fconst[cb+1]), 0.f);
        v.z = fmaxf(v.z + __ldg(&g_fconst[cb+2]), 0.f);
        v.w = fmaxf(v.w + __ldg(&g_fconst[cb+3]), 0.f);
        *(float4*)&g_feats[((size_t)b*NPIX + p0 + row)*EE + cb] = v;
    }
}

// ------------------------------------------------------------------
// per-(b,seg) mean/max pooling over pixel list; each thread owns 3 channels
__global__ void k_pool() {
    __shared__ int sp[256];
    int k = blockIdx.x;
    int b = k / MM;
    int tid = threadIdx.x;
    int cnt = g_cnt[k];
    int off = g_off[k];
    const float* fb = g_feats + (size_t)b*NPIX*EE;

    float s0=0.f, s1=0.f, s2=0.f, m0=0.f, m1=0.f, m2=0.f;
    for (int base = 0; base < cnt; base += 256) {
        int nchunk = min(256, cnt - base);
        __syncthreads();
        if (tid < nchunk) sp[tid] = g_plist[off + base + tid];
        __syncthreads();
        int i = 0;
        for (; i + 1 < nchunk; i += 2) {
            const float* f0 = fb + (size_t)sp[i]*EE + tid;
            const float* f1 = fb + (size_t)sp[i+1]*EE + tid;
            float a0 = f0[0], b0 = f0[256], c0v = f0[512];
            float a1 = f1[0], b1 = f1[256], c1v = f1[512];
            s0 += a0 + a1; s1 += b0 + b1; s2 += c0v + c1v;
            m0 = fmaxf(m0, fmaxf(a0, a1));
            m1 = fmaxf(m1, fmaxf(b0, b1));
            m2 = fmaxf(m2, fmaxf(c0v, c1v));
        }
        if (i < nchunk) {
            const float* f0 = fb + (size_t)sp[i]*EE + tid;
            float a0 = f0[0], b0 = f0[256], c0v = f0[512];
            s0 += a0; s1 += b0; s2 += c0v;
            m0 = fmaxf(m0, a0); m1 = fmaxf(m1, b0); m2 = fmaxf(m2, c0v);
        }
    }
    float n = fmaxf((float)cnt, 1.f);
    float* dst = g_concat + (size_t)k*1536;
    dst[tid]        = s0/n;  dst[256 + tid]  = s1/n;  dst[512 + tid]  = s2/n;
    dst[768 + tid]  = m0;    dst[1024 + tid] = m1;    dst[1280 + tid] = m2;
}

// ------------------------------------------------------------------
// fused = concat @ fusion_w^T + b, *W_k, + positional embedding
__global__ void k_fuse(const float* fw, const float* fbias, const float* pw,
                       const float* pb, const float* cent, float* out) {
    __shared__ float As[16][68];
    __shared__ float Bs[16][68];
    int tid = threadIdx.x;
    int d0 = blockIdx.x * 64;
    int r0 = blockIdx.y * 64;
    int tx = tid % 16, ty2 = tid / 16;

    float acc[4][4];
    #pragma unroll
    for (int i = 0; i < 4; i++)
        #pragma unroll
        for (int j = 0; j < 4; j++) acc[i][j] = 0.f;

    for (int kk = 0; kk < 2*EE; kk += 16) {
        {
            int ar = tid >> 2, ac4 = tid & 3;
            int r = r0 + ar;
            float4 v = make_float4(0.f,0.f,0.f,0.f);
            if (r < KK)
                v = ((const float4*)(g_concat + (size_t)r*1536 + kk))[ac4];
            As[ac4*4+0][ar] = v.x; As[ac4*4+1][ar] = v.y;
            As[ac4*4+2][ar] = v.z; As[ac4*4+3][ar] = v.w;
        }
        {
            int dd = tid >> 2, cc4 = tid & 3;
            float4 v = ((const float4*)(fw + (size_t)(d0 + dd)*1536 + kk))[cc4];
            Bs[cc4*4+0][dd] = v.x; Bs[cc4*4+1][dd] = v.y;
            Bs[cc4*4+2][dd] = v.z; Bs[cc4*4+3][dd] = v.w;
        }
        __syncthreads();
        #pragma unroll
        for (int q = 0; q < 16; q++) {
            float4 a = *(const float4*)&As[q][ty2*4];
            float4 bv = *(const float4*)&Bs[q][tx*4];
            const float* ap = (const float*)&a;
            const float* bp = (const float*)&bv;
            #pragma unroll
            for (int i = 0; i < 4; i++)
                #pragma unroll
                for (int j = 0; j < 4; j++)
                    acc[i][j] += ap[i] * bp[j];
        }
        __syncthreads();
    }

    #pragma unroll
    for (int i = 0; i < 4; i++) {
        int r = r0 + ty2*4 + i;
        if (r >= KK) continue;
        float wk = g_wk[r];
        float cx = __ldg(&cent[r*2 + 0]) * (1.f/224.f);
        float cy = __ldg(&cent[r*2 + 1]) * (1.f/224.f);
        #pragma unroll
        for (int j = 0; j < 4; j++) {
            int d = d0 + tx*4 + j;
            float v = (acc[i][j] + __ldg(&fbias[d])) * wk;
            v += cx*__ldg(&pw[d*2 + 0]) + cy*__ldg(&pw[d*2 + 1]) + __ldg(&pb[d]);
            out[(size_t)r*EE + d] = v;
        }
    }
}

// ------------------------------------------------------------------
extern "C" void kernel_launch(void* const* d_in, const int* in_sizes, int n_in,
                              void* d_out, int out_size) {
    const float* img   = (const float*)d_in[0];
    const int*   seg   = (const int*)d_in[1];
    const float* cent  = (const float*)d_in[2];
    const float* c1w   = (const float*)d_in[3];
    const float* c1b   = (const float*)d_in[4];
    const float* bn1g  = (const float*)d_in[5];
    const float* bn1b  = (const float*)d_in[6];
    const float* bn1m  = (const float*)d_in[7];
    const float* bn1v  = (const float*)d_in[8];
    const float* c2w   = (const float*)d_in[9];
    const float* c2b   = (const float*)d_in[10];
    const float* bn2g  = (const float*)d_in[11];
    const float* bn2b  = (const float*)d_in[12];
    const float* bn2m  = (const float*)d_in[13];
    const float* bn2v  = (const float*)d_in[14];
    const float* edgew = (const float*)d_in[15];
    const float* posw  = (const float*)d_in[16];
    const float* posb  = (const float*)d_in[17];
    const float* fusw  = (const float*)d_in[18];
    const float* fusb  = (const float*)d_in[19];
    float* out = (float*)d_out;
    (void)n_in; (void)in_sizes;

    const int FINAL_N = BB*MM*EE;
    int goff = (out_size >= FINAL_N + BB*NPIX)   ? FINAL_N : -1;
    int soff = (out_size >= FINAL_N + 2*BB*NPIX) ? FINAL_N + BB*NPIX : -1;

    cudaFuncSetAttribute(k_conv2_wmma, cudaFuncAttributeMaxDynamicSharedMemorySize, SMEM_W);

    k_zero<<<1024, 256>>>();
    k_prep_fconst<<<1, EE>>>(c2b, bn2g, bn2b, bn2m, bn2v);
    k_prep_wb<<<(9*EE*C1 + 255)/256, 256>>>(c2w, bn2g, bn2v);
    k_conv1<<<(BB*NPIX*8)/256, 256>>>(img, c1w, c1b, bn1g, bn1b, bn1m, bn1v);
    k_edge<<<BB*NPIX/256, 256>>>(img, seg, edgew, out, goff, soff);
    k_scan<<<1, 512>>>();
    k_scatter<<<BB*NPIX/256, 256>>>(seg);
    k_conv2_wmma<<<dim3(NPIX/128, EE/128, BB), 256, SMEM_W>>>();
    k_pool<<<KK, 256>>>();
    k_fuse<<<dim3(EE/64, (KK + 63)/64), 256>>>(fusw, fusb, posw, posb, cent, out);
}